// round 1
// baseline (speedup 1.0000x reference)
#include <cuda_runtime.h>

#define IMG     512
#define WSTRIP  128
#define HSEG    128
#define HALO    5
#define SROW    144   // 138 used, padded

// Fast reciprocal: integer-magic seed + 3 Newton iterations (no MUFU).
// den is always positive/normal here (sums of squares + constants).
static __device__ __forceinline__ float frcp(float x) {
    float y = __uint_as_float(0x7EF311C3u - __float_as_uint(x));
    y = y * (2.0f - x * y);
    y = y * (2.0f - x * y);
    y = y * (2.0f - x * y);
    return y;
}

__global__ void __launch_bounds__(128, 3)
ssim_fused_kernel(const float* __restrict__ A, const float* __restrict__ B,
                  const float* __restrict__ F, float* __restrict__ out,
                  float scale)
{
    // Gaussian(11, sigma=1.5), normalized — compile-time literals so ptxas
    // can emit FFMA-imm (rt=1) forms.
    constexpr float W[11] = {0.00102838f, 0.00759876f, 0.03600077f, 0.10936069f,
                             0.21300553f, 0.26601172f, 0.21300553f, 0.10936069f,
                             0.03600077f, 0.00759876f, 0.00102838f};
    constexpr float C1 = 0.0001f, C2 = 0.0009f;

    const int t  = threadIdx.x;
    const int x0 = blockIdx.x * WSTRIP;
    const int y0 = blockIdx.y * HSEG;
    const int y1 = y0 + HSEG;
    const size_t poff = (size_t)blockIdx.z * (size_t)(IMG * IMG);
    const float* a = A + poff;
    const float* b = B + poff;
    const float* f = F + poff;

    __shared__ float sA[2][SROW], sB[2][SROW], sF[2][SROW];

    // 8 channels x 11 pending output rows (ring, statically indexed)
    float acc[8][11];
#pragma unroll
    for (int c = 0; c < 8; ++c)
#pragma unroll
        for (int s = 0; s < 11; ++s) acc[c][s] = 0.0f;

    float ssum = 0.0f;

    const int ract_lo = (y0 - HALO) < 0 ? 0 : (y0 - HALO);
    const int ract_hi = (y1 + HALO - 1) > (IMG - 1) ? (IMG - 1) : (y1 + HALO - 1);

    const int  c0  = x0 - HALO + t;               // first load column
    const bool c0v = (c0 >= 0) && (c0 < IMG);
    const int  c1  = c0 + 128;                    // second batch (t<10)
    const bool c1v = (t < 10) && (c1 < IMG);

    // base: largest multiple of 11 <= y0-5 (y0-5 >= -5 > -11, so this works)
    const int base    = ((y0 - HALO + 11) / 11) * 11 - 11;
    const int nchunks = (y1 + HALO - base + 10) / 11;

    // prologue: stage row 'base' into buffer 0
    {
        const int r = base;
        float va = 0, vb = 0, vf = 0, ua = 0, ub = 0, uf = 0;
        if (r >= ract_lo && r <= ract_hi) {
            if (c0v) { const int i = r * IMG + c0; va = a[i]; vb = b[i]; vf = f[i]; }
            if (c1v) { const int i = r * IMG + c1; ua = a[i]; ub = b[i]; uf = f[i]; }
        }
        sA[0][t] = va; sB[0][t] = vb; sF[0][t] = vf;
        if (t < 10) { sA[0][t + 128] = ua; sB[0][t + 128] = ub; sF[0][t + 128] = uf; }
    }
    __syncthreads();

#pragma unroll 1
    for (int chk = 0; chk < nchunks; ++chk) {
        const int rbase = base + chk * 11;
#pragma unroll
        for (int p = 0; p < 11; ++p) {
            const int row = rbase + p;                 // row in smem buffer 'cur'
            const int cur = (row - base) & 1;

            // prefetch row+1 into registers (hides LDG under hconv compute)
            const int nr = row + 1;
            float va = 0, vb = 0, vf = 0, ua = 0, ub = 0, uf = 0;
            if (nr >= ract_lo && nr <= ract_hi) {
                if (c0v) { const int i = nr * IMG + c0; va = a[i]; vb = b[i]; vf = f[i]; }
                if (c1v) { const int i = nr * IMG + c1; ua = a[i]; ub = b[i]; uf = f[i]; }
            }

            if (row >= ract_lo && row <= ract_hi) {
                const float* ra = sA[cur];
                const float* rb = sB[cur];
                const float* rf = sF[cur];
                float hA = 0, hB = 0, hF = 0, hA2 = 0, hB2 = 0, hF2 = 0, hAF = 0, hBF = 0;
#pragma unroll
                for (int j = 0; j < 11; ++j) {
                    const float w  = W[j];
                    const float av = ra[t + j];
                    const float bv = rb[t + j];
                    const float fv = rf[t + j];
                    const float wa = w * av;      // mul-imm
                    const float wb = w * bv;
                    const float wf = w * fv;
                    hA  = fmaf(av, w, hA);        // fma-imm
                    hB  = fmaf(bv, w, hB);
                    hF  = fmaf(fv, w, hF);
                    hA2 = fmaf(wa, av, hA2);
                    hB2 = fmaf(wb, bv, hB2);
                    hF2 = fmaf(wf, fv, hF2);
                    hAF = fmaf(wa, fv, hAF);
                    hBF = fmaf(wb, fv, hBF);
                }
                // vertical scatter: this h-row contributes to 11 pending outputs
#pragma unroll
                for (int j = 0; j < 11; ++j) {
                    const int   slot = (p + 6 + j) % 11;   // compile-time constant
                    const float w    = W[j];               // symmetric window
                    acc[0][slot] = fmaf(hA , w, acc[0][slot]);
                    acc[1][slot] = fmaf(hB , w, acc[1][slot]);
                    acc[2][slot] = fmaf(hF , w, acc[2][slot]);
                    acc[3][slot] = fmaf(hA2, w, acc[3][slot]);
                    acc[4][slot] = fmaf(hB2, w, acc[4][slot]);
                    acc[5][slot] = fmaf(hF2, w, acc[5][slot]);
                    acc[6][slot] = fmaf(hAF, w, acc[6][slot]);
                    acc[7][slot] = fmaf(hBF, w, acc[7][slot]);
                }
            }

            // output row o = row - 5 is now complete
            {
                const int o  = row - HALO;
                const int sd = (p + 6) % 11;               // compile-time constant
                if (o >= y0 && o < y1) {
                    const float mu1  = acc[0][sd];
                    const float muB  = acc[1][sd];
                    const float mu2  = acc[2][sd];
                    const float eA2  = acc[3][sd];
                    const float eB2  = acc[4][sd];
                    const float eF2  = acc[5][sd];
                    const float eAF  = acc[6][sd];
                    const float eBF  = acc[7][sd];
                    const float mu2s = mu2 * mu2;
                    const float s2   = eF2 - mu2s;
                    {   // pair (A, F)
                        const float mu1s = mu1 * mu1;
                        const float m12  = mu1 * mu2;
                        const float s1   = eA2 - mu1s;
                        const float s12  = eAF - m12;
                        const float num  = fmaf(2.0f, m12, C1) * fmaf(2.0f, s12, C2);
                        const float den  = (mu1s + mu2s + C1) * (s1 + s2 + C2);
                        ssum += num * frcp(den);
                    }
                    {   // pair (B, F)
                        const float mu1s = muB * muB;
                        const float m12  = muB * mu2;
                        const float s1   = eB2 - mu1s;
                        const float s12  = eBF - m12;
                        const float num  = fmaf(2.0f, m12, C1) * fmaf(2.0f, s12, C2);
                        const float den  = (mu1s + mu2s + C1) * (s1 + s2 + C2);
                        ssum += num * frcp(den);
                    }
                }
                // recycle the ring slot for output row o+11
#pragma unroll
                for (int c = 0; c < 8; ++c) acc[c][sd] = 0.0f;
            }

            // stage prefetched row into the other buffer
            const int nxt = cur ^ 1;
            sA[nxt][t] = va; sB[nxt][t] = vb; sF[nxt][t] = vf;
            if (t < 10) { sA[nxt][t + 128] = ua; sB[nxt][t + 128] = ub; sF[nxt][t + 128] = uf; }
            __syncthreads();
        }
    }

    // block reduction -> single atomic per block
    const unsigned lane = t & 31u;
    const unsigned wid  = (unsigned)t >> 5;
#pragma unroll
    for (int off = 16; off; off >>= 1)
        ssum += __shfl_down_sync(0xffffffffu, ssum, off);
    __shared__ float wpart[4];
    if (lane == 0) wpart[wid] = ssum;
    __syncthreads();
    if (t == 0)
        atomicAdd(out, (wpart[0] + wpart[1] + wpart[2] + wpart[3]) * scale);
}

__global__ void zero_kernel(float* out) { *out = 0.0f; }

extern "C" void kernel_launch(void* const* d_in, const int* in_sizes, int n_in,
                              void* d_out, int out_size)
{
    const float* A = (const float*)d_in[0];
    const float* B = (const float*)d_in[1];
    const float* F = (const float*)d_in[2];
    float* out = (float*)d_out;

    const int nplanes = in_sizes[0] / (IMG * IMG);   // 48 for (16,3,512,512)
    const float scale = 0.5f / (float)in_sizes[0];   // 0.5 * (1/N) for each SSIM mean

    zero_kernel<<<1, 1>>>(out);
    dim3 grid(IMG / WSTRIP, IMG / HSEG, nplanes);
    ssim_fused_kernel<<<grid, 128>>>(A, B, F, out, scale);
}

// round 2
// speedup vs baseline: 1.2383x; 1.2383x over previous
#include <cuda_runtime.h>

#define IMG     512
#define WSTRIP  128
#define HSEG    128
#define HALO    5
#define SROW    138

typedef unsigned long long u64;

// ---- packed f32x2 helpers (Blackwell-only SASS: FFMA2/FMUL2/FADD2) ----
static __device__ __forceinline__ u64 pk(float lo, float hi) {
    u64 r; asm("mov.b64 %0, {%1, %2};" : "=l"(r) : "f"(lo), "f"(hi)); return r;
}
static __device__ __forceinline__ void upk(u64 v, float& lo, float& hi) {
    asm("mov.b64 {%0, %1}, %2;" : "=f"(lo), "=f"(hi) : "l"(v));
}
static __device__ __forceinline__ u64 fma2(u64 a, u64 b, u64 c) {
    u64 d; asm("fma.rn.f32x2 %0, %1, %2, %3;" : "=l"(d) : "l"(a), "l"(b), "l"(c)); return d;
}
static __device__ __forceinline__ u64 mul2(u64 a, u64 b) {
    u64 d; asm("mul.rn.f32x2 %0, %1, %2;" : "=l"(d) : "l"(a), "l"(b)); return d;
}
static __device__ __forceinline__ u64 add2(u64 a, u64 b) {
    u64 d; asm("add.rn.f32x2 %0, %1, %2;" : "=l"(d) : "l"(a), "l"(b)); return d;
}

__global__ void __launch_bounds__(128, 3)
ssim_fused_kernel(const float* __restrict__ A, const float* __restrict__ B,
                  const float* __restrict__ F, float* __restrict__ out,
                  float scale)
{
    constexpr float W[11] = {0.00102838f, 0.00759876f, 0.03600077f, 0.10936069f,
                             0.21300553f, 0.26601172f, 0.21300553f, 0.10936069f,
                             0.03600077f, 0.00759876f, 0.00102838f};
    constexpr float C1 = 0.0001f, C2 = 0.0009f;

    const int t  = threadIdx.x;
    const int x0 = blockIdx.x * WSTRIP;
    const int y0 = blockIdx.y * HSEG;
    const int y1 = y0 + HSEG;
    const size_t poff = (size_t)blockIdx.z * (size_t)(IMG * IMG);
    const float* ga = A + poff;
    const float* gb = B + poff;
    const float* gf = F + poff;

    // double-buffered 11-row chunks; pre-packed channels:
    //   sAB[.][.][c] = (a, b)   sFQ[.][.][c] = (f, f*f)
    __shared__ u64 sAB[2][11][SROW];
    __shared__ u64 sFQ[2][11][SROW];
    __shared__ float wpart[4];

    // packed (w,w) weights; symmetry -> 6 distinct registers
    u64 W2[6];
#pragma unroll
    for (int j = 0; j < 6; ++j) W2[j] = pk(W[j], W[j]);
    const u64 TWOv = pk(2.0f, 2.0f);
    const u64 C1v  = pk(C1, C1);
    const u64 C2v  = pk(C2, C2);
    const u64 NEG1 = pk(-1.0f, -1.0f);

    // vertical ring: 4 packed channels x 11 pending output rows
    u64 aAB[11], aAB2[11], aABF[11], aFF[11];
#pragma unroll
    for (int s = 0; s < 11; ++s) { aAB[s] = 0; aAB2[s] = 0; aABF[s] = 0; aFF[s] = 0; }

    float ssum = 0.0f;

    const int ract_lo = (y0 - HALO) < 0 ? 0 : (y0 - HALO);
    const int ract_hi = (y1 + HALO - 1) > (IMG - 1) ? (IMG - 1) : (y1 + HALO - 1);

    const int  c0  = x0 - HALO + t;
    const bool c0v = (c0 >= 0) && (c0 < IMG);
    const int  c1  = c0 + 128;
    const bool c1v = (t < 10) && (c1 < IMG);

    const int base    = ((y0 - HALO + 11) / 11) * 11 - 11;   // multiple of 11 <= y0-5
    const int nchunks = (y1 + HALO - base + 10) / 11;

    // ---- prologue: stage rows base..base+10 into buffer 0 ----
#pragma unroll
    for (int p = 0; p < 11; ++p) {
        const int r = base + p;
        float va = 0, vb = 0, vf = 0, ua = 0, ub = 0, uf = 0;
        if (r >= ract_lo && r <= ract_hi) {
            if (c0v) { const int i = r * IMG + c0; va = ga[i]; vb = gb[i]; vf = gf[i]; }
            if (c1v) { const int i = r * IMG + c1; ua = ga[i]; ub = gb[i]; uf = gf[i]; }
        }
        sAB[0][p][t] = pk(va, vb);
        sFQ[0][p][t] = pk(vf, vf * vf);
        if (t < 10) {
            sAB[0][p][t + 128] = pk(ua, ub);
            sFQ[0][p][t + 128] = pk(uf, uf * uf);
        }
    }
    __syncthreads();

#pragma unroll 1
    for (int chk = 0; chk < nchunks; ++chk) {
        const int rbase = base + chk * 11;
        const int bb = chk & 1, nb = bb ^ 1;
#pragma unroll
        for (int p = 0; p < 11; ++p) {
            const int row = rbase + p;

            // issue global loads for row+11 (next chunk, same phase slot)
            const int nr = row + 11;
            float va = 0, vb = 0, vf = 0, ua = 0, ub = 0, uf = 0;
            if (nr >= ract_lo && nr <= ract_hi) {
                if (c0v) { const int i = nr * IMG + c0; va = ga[i]; vb = gb[i]; vf = gf[i]; }
                if (c1v) { const int i = nr * IMG + c1; ua = ga[i]; ub = gb[i]; uf = gf[i]; }
            }

            if (row >= ract_lo && row <= ract_hi) {
                const u64* rab = sAB[bb][p];
                const u64* rfq = sFQ[bb][p];
                u64 hAB = 0, hAB2 = 0, hABF = 0, hFF = 0;
#pragma unroll
                for (int j = 0; j < 11; ++j) {
                    const u64 w2  = W2[j < 6 ? j : 10 - j];
                    const u64 vab = rab[t + j];
                    const u64 pf  = rfq[t + j];
                    hAB  = fma2(vab, w2, hAB);         // (Sa, Sb)
                    const u64 t1 = mul2(vab, w2);      // (w a, w b)
                    hAB2 = fma2(t1, vab, hAB2);        // (Sa2, Sb2)
                    hFF  = fma2(pf, w2, hFF);          // (Sf, Sf2)
                    float fl, fh; upk(pf, fl, fh);
                    const u64 vff = pk(fl, fl);        // (f, f)
                    hABF = fma2(t1, vff, hABF);        // (Saf, Sbf)
                }
                // vertical scatter into 11 pending outputs (static slots)
#pragma unroll
                for (int j = 0; j < 11; ++j) {
                    const int s  = (p + 6 + j) % 11;
                    const u64 w2 = W2[j < 6 ? j : 10 - j];
                    aAB [s] = fma2(hAB , w2, aAB [s]);
                    aAB2[s] = fma2(hAB2, w2, aAB2[s]);
                    aABF[s] = fma2(hABF, w2, aABF[s]);
                    aFF [s] = fma2(hFF , w2, aFF [s]);
                }
            }

            // output row o = row - 5 is complete in slot (p+6)%11
            {
                const int o  = row - HALO;
                const int sd = (p + 6) % 11;
                if (o >= y0 && o < y1) {
                    float muF, EF2; upk(aFF[sd], muF, EF2);
                    const float muF2 = muF * muF;
                    const float s2c2 = EF2 - muF2 + C2;       // sigma2 + C2
                    const u64 vmuF = pk(muF, muF);
                    const float mc  = muF2 + C1;
                    const u64 vmc  = pk(mc, mc);
                    const u64 vs2  = pk(s2c2, s2c2);

                    const u64 m12  = mul2(aAB[sd], vmuF);             // mu1*mu2
                    const u64 mu1s = mul2(aAB[sd], aAB[sd]);          // mu1^2
                    const u64 denl = add2(mu1s, vmc);                 // mu1^2+mu2^2+C1
                    const u64 denr = fma2(mu1s, NEG1, add2(aAB2[sd], vs2)); // s1+s2+C2
                    const u64 s12  = fma2(m12, NEG1, aABF[sd]);       // sigma12
                    const u64 numl = fma2(m12, TWOv, C1v);
                    const u64 numr = fma2(s12, TWOv, C2v);
                    const u64 num  = mul2(numl, numr);
                    const u64 den  = mul2(denl, denr);
                    float nA, nB, dA, dB;
                    upk(num, nA, nB); upk(den, dA, dB);
                    // ssimA + ssimB = (nA*dB + nB*dA) / (dA*dB): one MUFU rcp
                    ssum += __fdividef(fmaf(nA, dB, nB * dA), dA * dB);
                }
                aAB[sd] = 0; aAB2[sd] = 0; aABF[sd] = 0; aFF[sd] = 0;
            }

            // stage prefetched row into next buffer, same phase slot
            sAB[nb][p][t] = pk(va, vb);
            sFQ[nb][p][t] = pk(vf, vf * vf);
            if (t < 10) {
                sAB[nb][p][t + 128] = pk(ua, ub);
                sFQ[nb][p][t + 128] = pk(uf, uf * uf);
            }
        }
        __syncthreads();
    }

    // block reduction -> single atomic per block
    const unsigned lane = t & 31u;
    const unsigned wid  = (unsigned)t >> 5;
#pragma unroll
    for (int off = 16; off; off >>= 1)
        ssum += __shfl_down_sync(0xffffffffu, ssum, off);
    if (lane == 0) wpart[wid] = ssum;
    __syncthreads();
    if (t == 0)
        atomicAdd(out, (wpart[0] + wpart[1] + wpart[2] + wpart[3]) * scale);
}

__global__ void zero_kernel(float* out) { *out = 0.0f; }

extern "C" void kernel_launch(void* const* d_in, const int* in_sizes, int n_in,
                              void* d_out, int out_size)
{
    const float* A = (const float*)d_in[0];
    const float* B = (const float*)d_in[1];
    const float* F = (const float*)d_in[2];
    float* out = (float*)d_out;

    const int nplanes = in_sizes[0] / (IMG * IMG);   // 48
    const float scale = 0.5f / (float)in_sizes[0];

    zero_kernel<<<1, 1>>>(out);
    dim3 grid(IMG / WSTRIP, IMG / HSEG, nplanes);
    ssim_fused_kernel<<<grid, 128>>>(A, B, F, out, scale);
}